// round 3
// baseline (speedup 1.0000x reference)
#include <cuda_runtime.h>
#include <math.h>

#define BB 2
#define TT 2048
#define CC 1024
#define HQ 16
#define HKV 2
#define HD 64
#define MROWS (BB*TT)   // 4096

typedef unsigned long long u64;

// Scratch (device globals: allocation APIs are forbidden)
__device__ float g_q[BB*TT*HQ*HD];    // [b][t][h][d]  16 MB
__device__ float g_k[BB*TT*HKV*HD];   // [b][t][h][d]   2 MB
__device__ float g_v[BB*TT*HKV*HD];   //                2 MB
__device__ float g_y[BB*TT*HQ*HD];    // attention out 16 MB

// ---------------------------------------------------------------------------
// Packed fp32x2 helpers (Blackwell FFMA2 path)
// ---------------------------------------------------------------------------
__device__ __forceinline__ u64 pk2(float lo, float hi) {
    u64 r; asm("mov.b64 %0, {%1, %2};" : "=l"(r) : "f"(lo), "f"(hi)); return r;
}
__device__ __forceinline__ void upk2(u64 v, float& lo, float& hi) {
    asm("mov.b64 {%0, %1}, %2;" : "=f"(lo), "=f"(hi) : "l"(v));
}
__device__ __forceinline__ void ffma2(u64& d, u64 a, u64 b) {
    asm("fma.rn.f32x2 %0, %1, %2, %0;" : "+l"(d) : "l"(a), "l"(b));
}
__device__ __forceinline__ void fmul2(u64& d, u64 a) {
    asm("mul.rn.f32x2 %0, %0, %1;" : "+l"(d) : "l"(a));
}

// Swizzled [row][64] float tiles: 16B-chunk XOR swizzle, conflict-free for
// row-indexed-per-lane accesses, chunk-contiguous for vector loads.
__device__ __forceinline__ int swz4(int r, int chunk) {          // float4 chunk
    return r * 64 + ((chunk ^ (r & 15)) << 2);
}
__device__ __forceinline__ int swz1(int r, int c) {              // scalar
    return r * 64 + ((((c >> 2) ^ (r & 15)) << 2) | (c & 3));
}

// ---------------------------------------------------------------------------
// GEMM tile: out[m][n] = sum_k X[m][k]*W[n][k] + bias[n]   (+ optional RoPE)
// 128x128x16, 256 threads, 8x8 micro-tile, fp32x2 packed FMA, double-buffered.
// ropemode: 0 = none, 1 = rope (rc!=nullptr), postscale applied after.
// ---------------------------------------------------------------------------
__device__ __forceinline__ void gemm128_tile(
    const float* __restrict__ X, const float* __restrict__ W,
    const float* __restrict__ bias, float* __restrict__ out,
    int m0, int n0, int K, int ldo,
    const float* __restrict__ rc, int ropemode, float postscale)
{
    __shared__ float As[2][16][132];   // [buf][k][m]
    __shared__ float Bs[2][16][132];   // [buf][k][n]

    const int tid = threadIdx.x;
    const int tn = tid & 15, tm = tid >> 4;
    const int lr = tid >> 2;            // 0..63
    const int lk = (tid & 3) << 2;      // 0,4,8,12

    const float* Xp  = X + (size_t)(m0 + lr) * K + lk;
    const float* Xp2 = Xp + (size_t)64 * K;
    const float* Wp  = W + (size_t)(n0 + lr) * K + lk;
    const float* Wp2 = Wp + (size_t)64 * K;

    u64 acc[4][8];
    #pragma unroll
    for (int i = 0; i < 4; ++i)
        #pragma unroll
        for (int j = 0; j < 8; ++j) acc[i][j] = 0ull;

    float4 xa0 = *(const float4*)Xp;
    float4 xa1 = *(const float4*)Xp2;
    float4 wb0 = *(const float4*)Wp;
    float4 wb1 = *(const float4*)Wp2;
    #pragma unroll
    for (int j = 0; j < 4; ++j) {
        As[0][lk+j][lr]    = ((const float*)&xa0)[j];
        As[0][lk+j][lr+64] = ((const float*)&xa1)[j];
        Bs[0][lk+j][lr]    = ((const float*)&wb0)[j];
        Bs[0][lk+j][lr+64] = ((const float*)&wb1)[j];
    }
    __syncthreads();

    int buf = 0;
    for (int k0 = 16; k0 <= K; k0 += 16) {
        const bool more = (k0 < K);
        if (more) {
            xa0 = *(const float4*)(Xp  + k0);
            xa1 = *(const float4*)(Xp2 + k0);
            wb0 = *(const float4*)(Wp  + k0);
            wb1 = *(const float4*)(Wp2 + k0);
        }
        #pragma unroll
        for (int kk = 0; kk < 16; ++kk) {
            const float* as = &As[buf][kk][tm*4];
            const float* bs = &Bs[buf][kk][tn*4];
            ulonglong2 aA = *(const ulonglong2*)as;
            ulonglong2 aB = *(const ulonglong2*)(as + 64);
            float4 b0 = *(const float4*)bs;
            float4 b1 = *(const float4*)(bs + 64);
            u64 aa[4] = { aA.x, aA.y, aB.x, aB.y };
            u64 bb[8];
            bb[0] = pk2(b0.x, b0.x); bb[1] = pk2(b0.y, b0.y);
            bb[2] = pk2(b0.z, b0.z); bb[3] = pk2(b0.w, b0.w);
            bb[4] = pk2(b1.x, b1.x); bb[5] = pk2(b1.y, b1.y);
            bb[6] = pk2(b1.z, b1.z); bb[7] = pk2(b1.w, b1.w);
            #pragma unroll
            for (int i = 0; i < 4; ++i)
                #pragma unroll
                for (int j = 0; j < 8; ++j)
                    ffma2(acc[i][j], aa[i], bb[j]);
        }
        if (more) {
            #pragma unroll
            for (int j = 0; j < 4; ++j) {
                As[buf^1][lk+j][lr]    = ((const float*)&xa0)[j];
                As[buf^1][lk+j][lr+64] = ((const float*)&xa1)[j];
                Bs[buf^1][lk+j][lr]    = ((const float*)&wb0)[j];
                Bs[buf^1][lk+j][lr+64] = ((const float*)&wb1)[j];
            }
            __syncthreads();
            buf ^= 1;
        }
    }

    // epilogue (+bias, optional fused rope+scale)
    const float4 ba  = *(const float4*)(bias + n0 + tn*4);
    const float4 bb4 = *(const float4*)(bias + n0 + 64 + tn*4);
    #pragma unroll
    for (int rp = 0; rp < 4; ++rp) {
        const int r = m0 + ((rp < 2) ? (tm*4 + 2*rp) : (64 + tm*4 + 2*(rp-2)));
        float lo[8], hi[8];
        #pragma unroll
        for (int j = 0; j < 8; ++j) upk2(acc[rp][j], lo[j], hi[j]);
        #pragma unroll
        for (int half = 0; half < 2; ++half) {
            float* vals = half ? hi : lo;
            const int rr = r + half;
            const int t = rr & (TT - 1);
            #pragma unroll
            for (int cq = 0; cq < 2; ++cq) {       // column quads: n0+tn*4, n0+64+tn*4
                const int cb = n0 + cq*64 + tn*4;
                const float4 bv = cq ? bb4 : ba;
                float x = vals[cq*4+0] + bv.x;
                float y = vals[cq*4+1] + bv.y;
                float z = vals[cq*4+2] + bv.z;
                float w = vals[cq*4+3] + bv.w;
                if (ropemode) {
                    const float4 rcv = *(const float4*)(rc + t*HD + (cb & (HD-1)));
                    float ox = (x * rcv.y - y * rcv.x) * postscale;
                    float oy = (y * rcv.y + x * rcv.x) * postscale;
                    float oz = (z * rcv.w - w * rcv.z) * postscale;
                    float ow = (w * rcv.w + z * rcv.z) * postscale;
                    x = ox; y = oy; z = oz; w = ow;
                }
                float4 s; s.x = x; s.y = y; s.z = z; s.w = w;
                *(float4*)(out + (size_t)rr*ldo + cb) = s;
            }
        }
    }
}

// Fused QKV projection (+fused RoPE): grid.x: 0..7 -> Q cols, 8 -> K, 9 -> V
__global__ __launch_bounds__(256, 2) void qkv_gemm_kernel(
    const float* __restrict__ x, const float* __restrict__ rc,
    const float* __restrict__ Wq, const float* __restrict__ bq,
    const float* __restrict__ Wk, const float* __restrict__ bk,
    const float* __restrict__ Wv, const float* __restrict__ bv)
{
    const int nb = blockIdx.x;
    const float* W; const float* bias; float* out; int n0; int ldo;
    int ropemode; float ps;
    if (nb < 8)       { W = Wq; bias = bq; out = g_q; n0 = nb*128; ldo = HQ*HD;
                        ropemode = 1; ps = 1.0f / (float)HD; }
    else if (nb == 8) { W = Wk; bias = bk; out = g_k; n0 = 0;      ldo = HKV*HD;
                        ropemode = 1; ps = 1.0f; }
    else              { W = Wv; bias = bv; out = g_v; n0 = 0;      ldo = HKV*HD;
                        ropemode = 0; ps = 1.0f; }
    gemm128_tile(x, W, bias, out, blockIdx.y*128, n0, CC, ldo, rc, ropemode, ps);
}

__global__ __launch_bounds__(256, 2) void oproj_kernel(
    const float* __restrict__ Wo, const float* __restrict__ bo,
    float* __restrict__ out)
{
    gemm128_tile(g_y, Wo, bo, out, blockIdx.y*128, blockIdx.x*128, CC, CC,
                 nullptr, 0, 1.0f);
}

// ---------------------------------------------------------------------------
// Flash attention v3: swizzled smem (conflict-free), BK=64.
// grid (T/64, HQ, B), 256 threads. Warp w owns q-rows 8w..8w+7.
// Lane l owns k-cols l and l+32. fp32x2 packed over q-row pairs.
// ---------------------------------------------------------------------------
#define FLASH_SMEM (4*64*64*4)   // 64 KB

__global__ __launch_bounds__(256) void flash_kernel()
{
    extern __shared__ float fsm[];
    float* QsT = fsm;             // [d][row]   swizzled
    float* Ksm = fsm + 4096;      // [col][d]   swizzled
    float* Vsm = fsm + 8192;      // [row][d]   swizzled
    float* PsT = fsm + 12288;     // [col][row] swizzled

    const int qb = blockIdx.x, h = blockIdx.y, b = blockIdx.z;
    const int qs = qb * 64;
    const int hk = h / (HQ / HKV);
    const int tid = threadIdx.x, w = tid >> 5, l = tid & 31;

    // Load Q tile transposed into QsT[d][row]
    for (int it = tid; it < 64 * 16; it += 256) {
        int rr = it >> 4, c4 = (it & 15) * 4;
        float4 val = *(const float4*)(g_q +
            ((((size_t)b * TT + qs + rr) * HQ + h) * HD) + c4);
        QsT[swz1(c4+0, rr)] = val.x;
        QsT[swz1(c4+1, rr)] = val.y;
        QsT[swz1(c4+2, rr)] = val.z;
        QsT[swz1(c4+3, rr)] = val.w;
    }

    float m_[8], lsum[8];
    u64 O2[4][2];
    #pragma unroll
    for (int i = 0; i < 8; ++i) { m_[i] = -1e30f; lsum[i] = 0.f; }
    #pragma unroll
    for (int i = 0; i < 4; ++i) { O2[i][0] = 0ull; O2[i][1] = 0ull; }

    for (int kt = 0; kt <= qb; ++kt) {
        __syncthreads();
        for (int it = tid; it < 64 * 16; it += 256) {
            int rr = it >> 4, ch = it & 15;
            size_t base = ((((size_t)b * TT + kt * 64 + rr) * HKV + hk) * HD) + ch*4;
            *(float4*)&Ksm[swz4(rr, ch)] = *(const float4*)(g_k + base);
            *(float4*)&Vsm[swz4(rr, ch)] = *(const float4*)(g_v + base);
        }
        __syncthreads();

        // ---- S = Q.K^T, row-pair packed ----
        u64 s2[4][2];
        #pragma unroll
        for (int i = 0; i < 4; ++i) { s2[i][0] = 0ull; s2[i][1] = 0ull; }
        #pragma unroll 4
        for (int d4 = 0; d4 < 16; ++d4) {
            float4 k0v = *(const float4*)&Ksm[swz4(l, d4)];
            float4 k1v = *(const float4*)&Ksm[swz4(l+32, d4)];
            #pragma unroll
            for (int dd = 0; dd < 4; ++dd) {
                const int d = d4*4 + dd;
                const float kd0 = ((const float*)&k0v)[dd];
                const float kd1 = ((const float*)&k1v)[dd];
                u64 kp0 = pk2(kd0, kd0);
                u64 kp1 = pk2(kd1, kd1);
                ulonglong2 qA = *(const ulonglong2*)&QsT[swz4(d, 2*w)];
                ulonglong2 qB = *(const ulonglong2*)&QsT[swz4(d, 2*w+1)];
                ffma2(s2[0][0], qA.x, kp0); ffma2(s2[0][1], qA.x, kp1);
                ffma2(s2[1][0], qA.y, kp0); ffma2(s2[1][1], qA.y, kp1);
                ffma2(s2[2][0], qB.x, kp0); ffma2(s2[2][1], qB.x, kp1);
                ffma2(s2[3][0], qB.y, kp0); ffma2(s2[3][1], qB.y, kp1);
            }
        }

        float sA[8], sB[8];
        #pragma unroll
        for (int rp = 0; rp < 4; ++rp) {
            upk2(s2[rp][0], sA[2*rp], sA[2*rp+1]);
            upk2(s2[rp][1], sB[2*rp], sB[2*rp+1]);
        }

        // ---- online softmax ----
        const bool diag = (kt == qb);
        const int c0 = kt * 64;
        float corr[8];
        #pragma unroll
        for (int i = 0; i < 8; ++i) {
            const int grow = qs + 8*w + i;
            float sv0 = sA[i], sv1 = sB[i];
            if (diag) {
                if (c0 + l      > grow) sv0 = -1e30f;
                if (c0 + l + 32 > grow) sv1 = -1e30f;
            }
            float mx = fmaxf(sv0, sv1);
            #pragma unroll
            for (int off = 16; off; off >>= 1)
                mx = fmaxf(mx, __shfl_xor_sync(0xffffffffu, mx, off));
            const float newm = fmaxf(m_[i], mx);
            const float p0 = __expf(sv0 - newm);
            const float p1 = __expf(sv1 - newm);
            float rs = p0 + p1;
            #pragma unroll
            for (int off = 16; off; off >>= 1)
                rs += __shfl_xor_sync(0xffffffffu, rs, off);
            corr[i] = __expf(m_[i] - newm);
            lsum[i] = lsum[i] * corr[i] + rs;
            m_[i] = newm;
            PsT[swz1(l,    8*w + i)] = p0;
            PsT[swz1(l+32, 8*w + i)] = p1;
        }
        #pragma unroll
        for (int rp = 0; rp < 4; ++rp) {
            u64 cp = pk2(corr[2*rp], corr[2*rp+1]);
            fmul2(O2[rp][0], cp);
            fmul2(O2[rp][1], cp);
        }
        __syncwarp();

        // ---- O += P.V, row-pair packed ----
        #pragma unroll 8
        for (int j = 0; j < 64; ++j) {
            ulonglong2 pA = *(const ulonglong2*)&PsT[swz4(j, 2*w)];
            ulonglong2 pB = *(const ulonglong2*)&PsT[swz4(j, 2*w+1)];
            const float v0 = Vsm[swz1(j, l)];
            const float v1 = Vsm[swz1(j, l+32)];
            u64 vp0 = pk2(v0, v0);
            u64 vp1 = pk2(v1, v1);
            ffma2(O2[0][0], pA.x, vp0); ffma2(O2[0][1], pA.x, vp1);
            ffma2(O2[1][0], pA.y, vp0); ffma2(O2[1][1], pA.y, vp1);
            ffma2(O2[2][0], pB.x, vp0); ffma2(O2[2][1], pB.x, vp1);
            ffma2(O2[3][0], pB.y, vp0); ffma2(O2[3][1], pB.y, vp1);
        }
    }

    // normalize + write y [b][t][h][d]
    #pragma unroll
    for (int rp = 0; rp < 4; ++rp) {
        float o0lo, o0hi, o1lo, o1hi;
        upk2(O2[rp][0], o0lo, o0hi);
        upk2(O2[rp][1], o1lo, o1hi);
        const int r0 = qs + 8*w + 2*rp;
        const float inv0 = 1.f / lsum[2*rp];
        const float inv1 = 1.f / lsum[2*rp + 1];
        size_t base0 = (((size_t)b * TT + r0) * HQ + h) * HD;
        size_t base1 = (((size_t)b * TT + r0 + 1) * HQ + h) * HD;
        g_y[base0 + l]      = o0lo * inv0;
        g_y[base0 + l + 32] = o1lo * inv0;
        g_y[base1 + l]      = o0hi * inv1;
        g_y[base1 + l + 32] = o1hi * inv1;
    }
}

// ---------------------------------------------------------------------------
extern "C" void kernel_launch(void* const* d_in, const int* in_sizes, int n_in,
                              void* d_out, int out_size)
{
    const float* x  = (const float*)d_in[0];
    const float* rc = (const float*)d_in[1];
    const float* Wq = (const float*)d_in[2];
    const float* bq = (const float*)d_in[3];
    const float* Wk = (const float*)d_in[4];
    const float* bk = (const float*)d_in[5];
    const float* Wv = (const float*)d_in[6];
    const float* bv = (const float*)d_in[7];
    const float* Wo = (const float*)d_in[8];
    const float* bo = (const float*)d_in[9];
    float* out = (float*)d_out;

    cudaFuncSetAttribute(flash_kernel,
                         cudaFuncAttributeMaxDynamicSharedMemorySize, FLASH_SMEM);

    // Fused QKV projection + RoPE (+ folded scale^2 = 1/HD into q)
    qkv_gemm_kernel<<<dim3(10, MROWS / 128), 256>>>(x, rc, Wq, bq, Wk, bk, Wv, bv);

    // Causal flash attention
    flash_kernel<<<dim3(TT / 64, HQ, BB), 256, FLASH_SMEM>>>();

    // Output projection
    oproj_kernel<<<dim3(CC / 128, MROWS / 128), 256>>>(Wo, bo, out);
}

// round 5
// speedup vs baseline: 1.4498x; 1.4498x over previous
#include <cuda_runtime.h>
#include <cuda_bf16.h>
#include <stdint.h>

typedef unsigned long long u64;
typedef unsigned int u32;

#define BB 2
#define TT 2048
#define CC 1024
#define HQ 16
#define HKV 2
#define HD 64
#define MROWS (BB*TT)   // 4096

// ---------------------------------------------------------------------------
// Scratch (device globals; allocation APIs are forbidden)
// ---------------------------------------------------------------------------
__device__ float g_q[MROWS*HQ*HD];
__device__ float g_k[MROWS*HKV*HD];
__device__ float g_v[MROWS*HKV*HD];
__device__ float g_y[MROWS*HQ*HD];

__device__ __nv_bfloat16 g_xh[MROWS*CC], g_xl[MROWS*CC];
__device__ __nv_bfloat16 g_yh[MROWS*CC], g_yl[MROWS*CC];
__device__ __nv_bfloat16 g_wqh[CC*CC],  g_wql[CC*CC];
__device__ __nv_bfloat16 g_wkh[HKV*HD*CC], g_wkl[HKV*HD*CC];
__device__ __nv_bfloat16 g_wvh[HKV*HD*CC], g_wvl[HKV*HD*CC];
__device__ __nv_bfloat16 g_woh[CC*CC],  g_wol[CC*CC];

// ---------------------------------------------------------------------------
__device__ __forceinline__ u32 smem_to_u32(const void* p) {
    u32 a;
    asm("{ .reg .u64 tmp; cvta.to.shared.u64 tmp, %1; cvt.u32.u64 %0, tmp; }"
        : "=r"(a) : "l"(p));
    return a;
}
__device__ __forceinline__ void ldm_x4(u32* r, u32 addr) {
    asm volatile("ldmatrix.sync.aligned.m8n8.x4.shared.b16 {%0,%1,%2,%3}, [%4];"
        : "=r"(r[0]), "=r"(r[1]), "=r"(r[2]), "=r"(r[3]) : "r"(addr));
}
__device__ __forceinline__ void hmma(float* d, const u32* a, const u32* b) {
    asm volatile("mma.sync.aligned.m16n8k16.row.col.f32.bf16.bf16.f32 "
        "{%0,%1,%2,%3}, {%4,%5,%6,%7}, {%8,%9}, {%0,%1,%2,%3};"
        : "+f"(d[0]), "+f"(d[1]), "+f"(d[2]), "+f"(d[3])
        : "r"(a[0]), "r"(a[1]), "r"(a[2]), "r"(a[3]), "r"(b[0]), "r"(b[1]));
}

// ---------------------------------------------------------------------------
// Split fp32 -> (hi, lo) bf16
// ---------------------------------------------------------------------------
__global__ void split_kernel(const float* __restrict__ src,
                             __nv_bfloat16* __restrict__ h,
                             __nv_bfloat16* __restrict__ l, int n4)
{
    int i = blockIdx.x * blockDim.x + threadIdx.x;
    if (i >= n4) return;
    float4 v = ((const float4*)src)[i];
    float vv[4] = { v.x, v.y, v.z, v.w };
    __nv_bfloat162 hh[2], ll[2];
    #pragma unroll
    for (int j = 0; j < 2; ++j) {
        __nv_bfloat16 h0 = __float2bfloat16(vv[2*j]);
        __nv_bfloat16 h1 = __float2bfloat16(vv[2*j+1]);
        hh[j].x = h0; hh[j].y = h1;
        ll[j].x = __float2bfloat16(vv[2*j]   - __bfloat162float(h0));
        ll[j].y = __float2bfloat16(vv[2*j+1] - __bfloat162float(h1));
    }
    ((__nv_bfloat162*)h)[2*i]   = hh[0];
    ((__nv_bfloat162*)h)[2*i+1] = hh[1];
    ((__nv_bfloat162*)l)[2*i]   = ll[0];
    ((__nv_bfloat162*)l)[2*i+1] = ll[1];
}

// ---------------------------------------------------------------------------
// HMMA bf16 split-GEMM: out[128,128] = A[128,K].B[128,K]^T (+bias, opt rope)
// 256 threads (8 warps), warp tile 64x32 (4x4 m16n8k16), BK=64, double-buffer.
// smem rows padded to 144B (stride 36 words -> conflict-free ldmatrix).
// ---------------------------------------------------------------------------
#define SPB 144                         // smem row pitch (bytes) for 64 bf16
#define MAT_BYTES (128*SPB)             // 18432
#define STAGE_BYTES (4*MAT_BYTES)       // 73728
#define HMMA_SMEM (2*STAGE_BYTES)       // 147456

__device__ __forceinline__ void hmma_tile_128(
    const __nv_bfloat16* __restrict__ Ah, const __nv_bfloat16* __restrict__ Al,
    const __nv_bfloat16* __restrict__ Bh, const __nv_bfloat16* __restrict__ Bl,
    const float* __restrict__ bias, float* __restrict__ out,
    const float* __restrict__ rc,
    int m0, int n0, int ldo, int ropemode, float postscale)
{
    extern __shared__ char smem[];
    const u32 sbase = smem_to_u32(smem);
    const int tid = threadIdx.x;
    const int wid = tid >> 5, L = tid & 31;
    const int wm = (wid >> 2) * 64;          // warp m offset in tile
    const int wn = (wid & 3) * 32;           // warp n offset in tile

    // fragment base byte offsets (within one matrix buffer), lane-dependent
    const u32 aRow = (u32)(wm + (L & 15)) * SPB + ((L >> 4) & 1) * 16;
    const u32 bRow = (u32)(wn + (((L >> 4) & 1) << 3) + (L & 7)) * SPB
                   + ((L >> 3) & 1) * 16;

    float acc[4][4][4];
    #pragma unroll
    for (int i = 0; i < 4; ++i)
        #pragma unroll
        for (int j = 0; j < 4; ++j)
            #pragma unroll
            for (int c = 0; c < 4; ++c) acc[i][j][c] = 0.f;

    // loader mapping: 4 chunks per thread per matrix
    // it = tid + 256*i : row = it>>3 (0..127), ch = it&7 (16B chunk)
    float4 pA[4], pAl[4], pB[4], pBl[4];

    // prologue: slab 0
    #pragma unroll
    for (int i = 0; i < 4; ++i) {
        const int it = tid + 256*i;
        const int row = it >> 3, ch = it & 7;
        const size_t ga = (size_t)(m0 + row) * CC + ch*8;
        const size_t gb = (size_t)(n0 + row) * CC + ch*8;
        const u32 so = (u32)row * SPB + ch*16;
        *(float4*)(smem + so)               = *(const float4*)(Ah + ga);
        *(float4*)(smem + MAT_BYTES + so)   = *(const float4*)(Al + ga);
        *(float4*)(smem + 2*MAT_BYTES + so) = *(const float4*)(Bh + gb);
        *(float4*)(smem + 3*MAT_BYTES + so) = *(const float4*)(Bl + gb);
    }
    __syncthreads();

    const int nslab = CC / 64;   // 16
    for (int s = 0; s < nslab; ++s) {
        const int p = s & 1;
        const bool more = (s + 1 < nslab);
        if (more) {
            const int k0 = (s + 1) * 64;
            #pragma unroll
            for (int i = 0; i < 4; ++i) {
                const int it = tid + 256*i;
                const int row = it >> 3, ch = it & 7;
                const size_t ga = (size_t)(m0 + row) * CC + k0 + ch*8;
                const size_t gb = (size_t)(n0 + row) * CC + k0 + ch*8;
                pA[i]  = *(const float4*)(Ah + ga);
                pAl[i] = *(const float4*)(Al + ga);
                pB[i]  = *(const float4*)(Bh + gb);
                pBl[i] = *(const float4*)(Bl + gb);
            }
        }

        const u32 st = sbase + p * STAGE_BYTES;
        const u32 aAh = st + aRow;
        const u32 aAl = st + MAT_BYTES + aRow;
        const u32 aBh = st + 2*MAT_BYTES + bRow;
        const u32 aBl = st + 3*MAT_BYTES + bRow;

        #pragma unroll
        for (int ks = 0; ks < 4; ++ks) {
            u32 ah[4][4], al[4][4], bh[4][2], bl[4][2];
            #pragma unroll
            for (int mt = 0; mt < 4; ++mt) {
                ldm_x4(ah[mt], aAh + mt*(16*SPB) + ks*32);
                ldm_x4(al[mt], aAl + mt*(16*SPB) + ks*32);
            }
            #pragma unroll
            for (int np = 0; np < 2; ++np) {
                u32 r[4];
                ldm_x4(r, aBh + np*(16*SPB) + ks*32);
                bh[2*np][0] = r[0]; bh[2*np][1] = r[1];
                bh[2*np+1][0] = r[2]; bh[2*np+1][1] = r[3];
                ldm_x4(r, aBl + np*(16*SPB) + ks*32);
                bl[2*np][0] = r[0]; bl[2*np][1] = r[1];
                bl[2*np+1][0] = r[2]; bl[2*np+1][1] = r[3];
            }
            #pragma unroll
            for (int mt = 0; mt < 4; ++mt)
                #pragma unroll
                for (int nt = 0; nt < 4; ++nt) {
                    hmma(acc[mt][nt], ah[mt], bh[nt]);
                    hmma(acc[mt][nt], ah[mt], bl[nt]);
                    hmma(acc[mt][nt], al[mt], bh[nt]);
                }
        }

        if (more) {
            char* dst = smem + (p ^ 1) * STAGE_BYTES;
            #pragma unroll
            for (int i = 0; i < 4; ++i) {
                const int it = tid + 256*i;
                const int row = it >> 3, ch = it & 7;
                const u32 so = (u32)row * SPB + ch*16;
                *(float4*)(dst + so)               = pA[i];
                *(float4*)(dst + MAT_BYTES + so)   = pAl[i];
                *(float4*)(dst + 2*MAT_BYTES + so) = pB[i];
                *(float4*)(dst + 3*MAT_BYTES + so) = pBl[i];
            }
            __syncthreads();
        }
    }

    // Epilogue: D fragment c0,c1 -> (row g, cols n,n+1); c2,c3 -> row g+8.
    #pragma unroll
    for (int mt = 0; mt < 4; ++mt) {
        #pragma unroll
        for (int nt = 0; nt < 4; ++nt) {
            const int n = n0 + wn + nt*8 + (L & 3) * 2;
            const float2 bv = *(const float2*)(bias + n);
            #pragma unroll
            for (int half = 0; half < 2; ++half) {
                const int r = m0 + wm + mt*16 + (L >> 2) + half*8;
                float v0 = acc[mt][nt][2*half]   + bv.x;
                float v1 = acc[mt][nt][2*half+1] + bv.y;
                if (ropemode) {
                    const int t = r & (TT - 1);
                    const int d = n & (HD - 1);
                    const float2 rcv = *(const float2*)(rc + t*HD + d);
                    const float o0 = (v0 * rcv.y - v1 * rcv.x) * postscale;
                    const float o1 = (v1 * rcv.y + v0 * rcv.x) * postscale;
                    v0 = o0; v1 = o1;
                }
                float2 sv; sv.x = v0; sv.y = v1;
                *(float2*)(out + (size_t)r * ldo + n) = sv;
            }
        }
    }
}

// grid (10, 32): x 0..7 -> Q col tiles, 8 -> K, 9 -> V
__global__ __launch_bounds__(256) void qkv_hmma_kernel(
    const float* __restrict__ rc,
    const float* __restrict__ bq, const float* __restrict__ bk,
    const float* __restrict__ bv)
{
    const int nb = blockIdx.x, m0 = blockIdx.y * 128;
    if (nb < 8)
        hmma_tile_128(g_xh, g_xl, g_wqh, g_wql, bq, g_q, rc,
                      m0, nb * 128, HQ * HD, 1, 1.0f / (float)HD);
    else if (nb == 8)
        hmma_tile_128(g_xh, g_xl, g_wkh, g_wkl, bk, g_k, rc,
                      m0, 0, HKV * HD, 1, 1.0f);
    else
        hmma_tile_128(g_xh, g_xl, g_wvh, g_wvl, bv, g_v, rc,
                      m0, 0, HKV * HD, 0, 1.0f);
}

__global__ __launch_bounds__(256) void oproj_hmma_kernel(
    const float* __restrict__ bo, float* __restrict__ out)
{
    hmma_tile_128(g_yh, g_yl, g_woh, g_wol, bo, out, nullptr,
                  blockIdx.y * 128, blockIdx.x * 128, CC, 0, 1.0f);
}

// ---------------------------------------------------------------------------
// fp32x2 helpers for flash
// ---------------------------------------------------------------------------
__device__ __forceinline__ u64 pk2(float lo, float hi) {
    u64 r; asm("mov.b64 %0, {%1, %2};" : "=l"(r) : "f"(lo), "f"(hi)); return r;
}
__device__ __forceinline__ void upk2(u64 v, float& lo, float& hi) {
    asm("mov.b64 {%0, %1}, %2;" : "=f"(lo), "=f"(hi) : "l"(v));
}
__device__ __forceinline__ void ffma2(u64& d, u64 a, u64 b) {
    asm("fma.rn.f32x2 %0, %1, %2, %0;" : "+l"(d) : "l"(a), "l"(b));
}
__device__ __forceinline__ void fmul2(u64& d, u64 a) {
    asm("mul.rn.f32x2 %0, %0, %1;" : "+l"(d) : "l"(a));
}

// ---------------------------------------------------------------------------
// Flash attention (round-2 version, measured 648us). BK=64, 256 threads.
// ---------------------------------------------------------------------------
#define FPAD 68
#define FLASH_SMEM (4*64*FPAD*4)

__global__ __launch_bounds__(256) void flash_kernel()
{
    extern __shared__ float fsm[];
    float* QsT = fsm;                 // [64][68]  QsT[d][row]
    float* Ksm = fsm + 64*FPAD;       // [64][68]  Ks[col][d]
    float* Vsm = fsm + 2*64*FPAD;     // [64][68]  Vs[row][d]
    float* PsT = fsm + 3*64*FPAD;     // [64][68]  PsT[col][row]

    const int qb = blockIdx.x, h = blockIdx.y, b = blockIdx.z;
    const int qs = qb * 64;
    const int hk = h / (HQ / HKV);
    const int tid = threadIdx.x, w = tid >> 5, l = tid & 31;

    for (int it = tid; it < 64 * 16; it += 256) {
        int rr = it >> 4, c4 = (it & 15) * 4;
        float4 val = *(const float4*)(g_q +
            ((((size_t)b * TT + qs + rr) * HQ + h) * HD) + c4);
        QsT[(c4+0)*FPAD + rr] = val.x;
        QsT[(c4+1)*FPAD + rr] = val.y;
        QsT[(c4+2)*FPAD + rr] = val.z;
        QsT[(c4+3)*FPAD + rr] = val.w;
    }

    float m_[8], lsum[8];
    u64 O2[4][2];
    #pragma unroll
    for (int i = 0; i < 8; ++i) { m_[i] = -1e30f; lsum[i] = 0.f; }
    #pragma unroll
    for (int i = 0; i < 4; ++i) { O2[i][0] = 0ull; O2[i][1] = 0ull; }

    for (int kt = 0; kt <= qb; ++kt) {
        __syncthreads();
        for (int it = tid; it < 64 * 16; it += 256) {
            int rr = it >> 4, c4 = (it & 15) * 4;
            size_t base = ((((size_t)b * TT + kt * 64 + rr) * HKV + hk) * HD) + c4;
            *(float4*)&Ksm[rr*FPAD + c4] = *(const float4*)(g_k + base);
            *(float4*)&Vsm[rr*FPAD + c4] = *(const float4*)(g_v + base);
        }
        __syncthreads();

        u64 s2[4][2];
        #pragma unroll
        for (int i = 0; i < 4; ++i) { s2[i][0] = 0ull; s2[i][1] = 0ull; }
        #pragma unroll 4
        for (int d4 = 0; d4 < 16; ++d4) {
            float4 k0v = *(const float4*)&Ksm[l*FPAD + d4*4];
            float4 k1v = *(const float4*)&Ksm[(l+32)*FPAD + d4*4];
            #pragma unroll
            for (int dd = 0; dd < 4; ++dd) {
                const int d = d4*4 + dd;
                const float kd0 = ((const float*)&k0v)[dd];
                const float kd1 = ((const float*)&k1v)[dd];
                u64 kp0 = pk2(kd0, kd0);
                u64 kp1 = pk2(kd1, kd1);
                ulonglong2 qA = *(const ulonglong2*)&QsT[d*FPAD + 8*w];
                ulonglong2 qB = *(const ulonglong2*)&QsT[d*FPAD + 8*w + 4];
                ffma2(s2[0][0], qA.x, kp0); ffma2(s2[0][1], qA.x, kp1);
                ffma2(s2[1][0], qA.y, kp0); ffma2(s2[1][1], qA.y, kp1);
                ffma2(s2[2][0], qB.x, kp0); ffma2(s2[2][1], qB.x, kp1);
                ffma2(s2[3][0], qB.y, kp0); ffma2(s2[3][1], qB.y, kp1);
            }
        }

        float sA[8], sB[8];
        #pragma unroll
        for (int rp = 0; rp < 4; ++rp) {
            upk2(s2[rp][0], sA[2*rp], sA[2*rp+1]);
            upk2(s2[rp][1], sB[2*rp], sB[2*rp+1]);
        }

        const bool diag = (kt == qb);
        const int c0 = kt * 64;
        float corr[8];
        #pragma unroll
        for (int i = 0; i < 8; ++i) {
            const int grow = qs + 8*w + i;
            float sv0 = sA[i], sv1 = sB[i];
            if (diag) {
                if (c0 + l      > grow) sv0 = -1e30f;
                if (c0 + l + 32 > grow) sv1 = -1e30f;
            }
            float mx = fmaxf(sv0, sv1);
            #pragma unroll
            for (int off = 16; off; off >>= 1)
                mx = fmaxf(mx, __shfl_xor_sync(0xffffffffu, mx, off));
            const float newm = fmaxf(m_[i], mx);
            const float p0 = __expf(sv0 - newm);
            const float p1 = __expf(sv1 - newm);
            float rs = p0 + p1;
            #pragma unroll
            for (int off = 16; off; off >>= 1)
                rs += __shfl_xor_sync(0xffffffffu, rs, off);
            corr[i] = __expf(m_[i] - newm);
            lsum[i] = lsum[i] * corr[i] + rs;
            m_[i] = newm;
            PsT[l*FPAD + 8*w + i]      = p0;
            PsT[(l+32)*FPAD + 8*w + i] = p1;
        }
        #pragma unroll
        for (int rp = 0; rp < 4; ++rp) {
            u64 cp = pk2(corr[2*rp], corr[2*rp+1]);
            fmul2(O2[rp][0], cp);
            fmul2(O2[rp][1], cp);
        }
        __syncwarp();

        #pragma unroll 8
        for (int j = 0; j < 64; ++j) {
            ulonglong2 pA = *(const ulonglong2*)&PsT[j*FPAD + 8*w];
            ulonglong2 pB = *(const ulonglong2*)&PsT[j*FPAD + 8*w + 4];
            const float v0 = Vsm[j*FPAD + l];
            const float v1 = Vsm[j*FPAD + l + 32];
            u64 vp0 = pk2(v0, v0);
            u64 vp1 = pk2(v1, v1);
            ffma2(O2[0][0], pA.x, vp0); ffma2(O2[0][1], pA.x, vp1);
            ffma2(O2[1][0], pA.y, vp0); ffma2(O2[1][1], pA.y, vp1);
            ffma2(O2[2][0], pB.x, vp0); ffma2(O2[2][1], pB.x, vp1);
            ffma2(O2[3][0], pB.y, vp0); ffma2(O2[3][1], pB.y, vp1);
        }
    }

    #pragma unroll
    for (int rp = 0; rp < 4; ++rp) {
        float o0lo, o0hi, o1lo, o1hi;
        upk2(O2[rp][0], o0lo, o0hi);
        upk2(O2[rp][1], o1lo, o1hi);
        const int r0 = qs + 8*w + 2*rp;
        const float inv0 = 1.f / lsum[2*rp];
        const float inv1 = 1.f / lsum[2*rp + 1];
        size_t base0 = (((size_t)b * TT + r0) * HQ + h) * HD;
        size_t base1 = (((size_t)b * TT + r0 + 1) * HQ + h) * HD;
        g_y[base0 + l]      = o0lo * inv0;
        g_y[base0 + l + 32] = o1lo * inv0;
        g_y[base1 + l]      = o0hi * inv1;
        g_y[base1 + l + 32] = o1hi * inv1;
    }
}

// ---------------------------------------------------------------------------
extern "C" void kernel_launch(void* const* d_in, const int* in_sizes, int n_in,
                              void* d_out, int out_size)
{
    const float* x  = (const float*)d_in[0];
    const float* rc = (const float*)d_in[1];
    const float* Wq = (const float*)d_in[2];
    const float* bq = (const float*)d_in[3];
    const float* Wk = (const float*)d_in[4];
    const float* bk = (const float*)d_in[5];
    const float* Wv = (const float*)d_in[6];
    const float* bv = (const float*)d_in[7];
    const float* Wo = (const float*)d_in[8];
    const float* bo = (const float*)d_in[9];
    float* out = (float*)d_out;

    __nv_bfloat16 *xh, *xl, *yh, *yl, *wqh, *wql, *wkh, *wkl, *wvh, *wvl, *woh, *wol;
    float* yb;
    cudaGetSymbolAddress((void**)&xh,  g_xh);  cudaGetSymbolAddress((void**)&xl,  g_xl);
    cudaGetSymbolAddress((void**)&yh,  g_yh);  cudaGetSymbolAddress((void**)&yl,  g_yl);
    cudaGetSymbolAddress((void**)&wqh, g_wqh); cudaGetSymbolAddress((void**)&wql, g_wql);
    cudaGetSymbolAddress((void**)&wkh, g_wkh); cudaGetSymbolAddress((void**)&wkl, g_wkl);
    cudaGetSymbolAddress((void**)&wvh, g_wvh); cudaGetSymbolAddress((void**)&wvl, g_wvl);
    cudaGetSymbolAddress((void**)&woh, g_woh); cudaGetSymbolAddress((void**)&wol, g_wol);
    cudaGetSymbolAddress((void**)&yb,  g_y);

    cudaFuncSetAttribute(qkv_hmma_kernel,
                         cudaFuncAttributeMaxDynamicSharedMemorySize, HMMA_SMEM);
    cudaFuncSetAttribute(oproj_hmma_kernel,
                         cudaFuncAttributeMaxDynamicSharedMemorySize, HMMA_SMEM);
    cudaFuncSetAttribute(flash_kernel,
                         cudaFuncAttributeMaxDynamicSharedMemorySize, FLASH_SMEM);

    // Split fp32 -> bf16 (hi, lo)
    split_kernel<<<(MROWS*CC/4 + 255)/256, 256>>>(x,  xh,  xl,  MROWS*CC/4);
    split_kernel<<<(CC*CC/4 + 255)/256, 256>>>(Wq, wqh, wql, CC*CC/4);
    split_kernel<<<(HKV*HD*CC/4 + 255)/256, 256>>>(Wk, wkh, wkl, HKV*HD*CC/4);
    split_kernel<<<(HKV*HD*CC/4 + 255)/256, 256>>>(Wv, wvh, wvl, HKV*HD*CC/4);
    split_kernel<<<(CC*CC/4 + 255)/256, 256>>>(Wo, woh, wol, CC*CC/4);

    // QKV projection + bias + RoPE (HMMA, split-bf16)
    qkv_hmma_kernel<<<dim3(10, MROWS/128), 256, HMMA_SMEM>>>(rc, bq, bk, bv);

    // Causal flash attention (fp32 / FFMA2)
    flash_kernel<<<dim3(TT/64, HQ, BB), 256, FLASH_SMEM>>>();

    // Output projection (HMMA, split-bf16)
    split_kernel<<<(MROWS*CC/4 + 255)/256, 256>>>(yb, yh, yl, MROWS*CC/4);
    oproj_hmma_kernel<<<dim3(CC/128, MROWS/128), 256, HMMA_SMEM>>>(bo, out);
}

// round 7
// speedup vs baseline: 2.8594x; 1.9722x over previous
#include <cuda_runtime.h>
#include <cuda_bf16.h>
#include <stdint.h>

typedef unsigned long long u64;
typedef unsigned int u32;

#define BB 2
#define TT 2048
#define CC 1024
#define HQ 16
#define HKV 2
#define HD 64
#define MROWS (BB*TT)   // 4096

// ---------------------------------------------------------------------------
// Scratch (device globals; allocation APIs are forbidden)
// ---------------------------------------------------------------------------
__device__ float g_y[MROWS*CC];                       // attention out (fp32)

__device__ __nv_bfloat16 g_xh[MROWS*CC], g_xl[MROWS*CC];
__device__ __nv_bfloat16 g_yh[MROWS*CC], g_yl[MROWS*CC];
__device__ __nv_bfloat16 g_wqh[CC*CC],  g_wql[CC*CC];
__device__ __nv_bfloat16 g_wkh[HKV*HD*CC], g_wkl[HKV*HD*CC];
__device__ __nv_bfloat16 g_wvh[HKV*HD*CC], g_wvl[HKV*HD*CC];
__device__ __nv_bfloat16 g_woh[CC*CC],  g_wol[CC*CC];

// split-bf16 Q/K (row-major) and V (transposed [b][hk][d][t])
__device__ __nv_bfloat16 g_qbh[MROWS*HQ*HD],  g_qbl[MROWS*HQ*HD];
__device__ __nv_bfloat16 g_kbh[MROWS*HKV*HD], g_kbl[MROWS*HKV*HD];
__device__ __nv_bfloat16 g_vth[BB*HKV*HD*TT], g_vtl[BB*HKV*HD*TT];

// ---------------------------------------------------------------------------
__device__ __forceinline__ u32 smem_to_u32(const void* p) {
    u32 a;
    asm("{ .reg .u64 tmp; cvta.to.shared.u64 tmp, %1; cvt.u32.u64 %0, tmp; }"
        : "=r"(a) : "l"(p));
    return a;
}
__device__ __forceinline__ void ldm_x4(u32* r, u32 addr) {
    asm volatile("ldmatrix.sync.aligned.m8n8.x4.shared.b16 {%0,%1,%2,%3}, [%4];"
        : "=r"(r[0]), "=r"(r[1]), "=r"(r[2]), "=r"(r[3]) : "r"(addr));
}
__device__ __forceinline__ void hmma(float* d, const u32* a, const u32* b) {
    asm volatile("mma.sync.aligned.m16n8k16.row.col.f32.bf16.bf16.f32 "
        "{%0,%1,%2,%3}, {%4,%5,%6,%7}, {%8,%9}, {%0,%1,%2,%3};"
        : "+f"(d[0]), "+f"(d[1]), "+f"(d[2]), "+f"(d[3])
        : "r"(a[0]), "r"(a[1]), "r"(a[2]), "r"(a[3]), "r"(b[0]), "r"(b[1]));
}
// pack: result.hi = bf16(hi), result.lo = bf16(lo)
__device__ __forceinline__ u32 cvt2(float hi, float lo) {
    u32 r; asm("cvt.rn.bf16x2.f32 %0, %1, %2;" : "=r"(r) : "f"(hi), "f"(lo));
    return r;
}

// ---------------------------------------------------------------------------
// Split fp32 -> (hi, lo) bf16
// ---------------------------------------------------------------------------
__global__ void split_kernel(const float* __restrict__ src,
                             __nv_bfloat16* __restrict__ h,
                             __nv_bfloat16* __restrict__ l, int n4)
{
    int i = blockIdx.x * blockDim.x + threadIdx.x;
    if (i >= n4) return;
    float4 v = ((const float4*)src)[i];
    float vv[4] = { v.x, v.y, v.z, v.w };
    __nv_bfloat162 hh[2], ll[2];
    #pragma unroll
    for (int j = 0; j < 2; ++j) {
        __nv_bfloat16 h0 = __float2bfloat16(vv[2*j]);
        __nv_bfloat16 h1 = __float2bfloat16(vv[2*j+1]);
        hh[j].x = h0; hh[j].y = h1;
        ll[j].x = __float2bfloat16(vv[2*j]   - __bfloat162float(h0));
        ll[j].y = __float2bfloat16(vv[2*j+1] - __bfloat162float(h1));
    }
    ((__nv_bfloat162*)h)[2*i]   = hh[0];
    ((__nv_bfloat162*)h)[2*i+1] = hh[1];
    ((__nv_bfloat162*)l)[2*i]   = ll[0];
    ((__nv_bfloat162*)l)[2*i+1] = ll[1];
}

// ---------------------------------------------------------------------------
// HMMA bf16 split-GEMM tile: acc[128,128] = A[128,K].B[128,K]^T (+bias)
// mode 0: fp32 out (no rope)
// mode 1: rope + split-bf16 row-major out (Q, K)
// mode 2: split-bf16 transposed out for V ([b][hk][d][t])
// ---------------------------------------------------------------------------
#define SPB 144
#define MAT_BYTES (128*SPB)
#define STAGE_BYTES (4*MAT_BYTES)
#define HMMA_SMEM (2*STAGE_BYTES)       // 147456

__device__ __forceinline__ void hmma_tile_128(
    const __nv_bfloat16* __restrict__ Ah, const __nv_bfloat16* __restrict__ Al,
    const __nv_bfloat16* __restrict__ Bh, const __nv_bfloat16* __restrict__ Bl,
    const float* __restrict__ bias, const float* __restrict__ rc,
    int m0, int n0, int ldo, int mode, float postscale,
    float* __restrict__ outf,
    __nv_bfloat16* __restrict__ outh, __nv_bfloat16* __restrict__ outl)
{
    extern __shared__ char smem[];
    const u32 sbase = smem_to_u32(smem);
    const int tid = threadIdx.x;
    const int wid = tid >> 5, L = tid & 31;
    const int wm = (wid >> 2) * 64;
    const int wn = (wid & 3) * 32;

    const u32 aRow = (u32)(wm + (L & 15)) * SPB + ((L >> 4) & 1) * 16;
    const u32 bRow = (u32)(wn + (((L >> 4) & 1) << 3) + (L & 7)) * SPB
                   + ((L >> 3) & 1) * 16;

    float acc[4][4][4];
    #pragma unroll
    for (int i = 0; i < 4; ++i)
        #pragma unroll
        for (int j = 0; j < 4; ++j)
            #pragma unroll
            for (int c = 0; c < 4; ++c) acc[i][j][c] = 0.f;

    float4 pA[4], pAl[4], pB[4], pBl[4];

    #pragma unroll
    for (int i = 0; i < 4; ++i) {
        const int it = tid + 256*i;
        const int row = it >> 3, ch = it & 7;
        const size_t ga = (size_t)(m0 + row) * CC + ch*8;
        const size_t gb = (size_t)(n0 + row) * CC + ch*8;
        const u32 so = (u32)row * SPB + ch*16;
        *(float4*)(smem + so)               = *(const float4*)(Ah + ga);
        *(float4*)(smem + MAT_BYTES + so)   = *(const float4*)(Al + ga);
        *(float4*)(smem + 2*MAT_BYTES + so) = *(const float4*)(Bh + gb);
        *(float4*)(smem + 3*MAT_BYTES + so) = *(const float4*)(Bl + gb);
    }
    __syncthreads();

    const int nslab = CC / 64;
    for (int s = 0; s < nslab; ++s) {
        const int p = s & 1;
        const bool more = (s + 1 < nslab);
        if (more) {
            const int k0 = (s + 1) * 64;
            #pragma unroll
            for (int i = 0; i < 4; ++i) {
                const int it = tid + 256*i;
                const int row = it >> 3, ch = it & 7;
                const size_t ga = (size_t)(m0 + row) * CC + k0 + ch*8;
                const size_t gb = (size_t)(n0 + row) * CC + k0 + ch*8;
                pA[i]  = *(const float4*)(Ah + ga);
                pAl[i] = *(const float4*)(Al + ga);
                pB[i]  = *(const float4*)(Bh + gb);
                pBl[i] = *(const float4*)(Bl + gb);
            }
        }

        const u32 st = sbase + p * STAGE_BYTES;
        const u32 aAh = st + aRow;
        const u32 aAl = st + MAT_BYTES + aRow;
        const u32 aBh = st + 2*MAT_BYTES + bRow;
        const u32 aBl = st + 3*MAT_BYTES + bRow;

        #pragma unroll
        for (int ks = 0; ks < 4; ++ks) {
            u32 ah[4][4], al[4][4], bh[4][2], bl[4][2];
            #pragma unroll
            for (int mt = 0; mt < 4; ++mt) {
                ldm_x4(ah[mt], aAh + mt*(16*SPB) + ks*32);
                ldm_x4(al[mt], aAl + mt*(16*SPB) + ks*32);
            }
            #pragma unroll
            for (int np = 0; np < 2; ++np) {
                u32 r[4];
                ldm_x4(r, aBh + np*(16*SPB) + ks*32);
                bh[2*np][0] = r[0]; bh[2*np][1] = r[1];
                bh[2*np+1][0] = r[2]; bh[2*np+1][1] = r[3];
                ldm_x4(r, aBl + np*(16*SPB) + ks*32);
                bl[2*np][0] = r[0]; bl[2*np][1] = r[1];
                bl[2*np+1][0] = r[2]; bl[2*np+1][1] = r[3];
            }
            #pragma unroll
            for (int mt = 0; mt < 4; ++mt)
                #pragma unroll
                for (int nt = 0; nt < 4; ++nt) {
                    hmma(acc[mt][nt], ah[mt], bh[nt]);
                    hmma(acc[mt][nt], ah[mt], bl[nt]);
                    hmma(acc[mt][nt], al[mt], bh[nt]);
                }
        }

        if (more) {
            char* dst = smem + (p ^ 1) * STAGE_BYTES;
            #pragma unroll
            for (int i = 0; i < 4; ++i) {
                const int it = tid + 256*i;
                const int row = it >> 3, ch = it & 7;
                const u32 so = (u32)row * SPB + ch*16;
                *(float4*)(dst + so)               = pA[i];
                *(float4*)(dst + MAT_BYTES + so)   = pAl[i];
                *(float4*)(dst + 2*MAT_BYTES + so) = pB[i];
                *(float4*)(dst + 3*MAT_BYTES + so) = pBl[i];
            }
            __syncthreads();
        }
    }

    // Epilogue
    #pragma unroll
    for (int mt = 0; mt < 4; ++mt) {
        #pragma unroll
        for (int nt = 0; nt < 4; ++nt) {
            const int n = n0 + wn + nt*8 + (L & 3) * 2;
            const float2 bv = *(const float2*)(bias + n);
            #pragma unroll
            for (int half = 0; half < 2; ++half) {
                const int r = m0 + wm + mt*16 + (L >> 2) + half*8;
                float v0 = acc[mt][nt][2*half]   + bv.x;
                float v1 = acc[mt][nt][2*half+1] + bv.y;
                if (mode == 1) {
                    const int t = r & (TT - 1);
                    const int d = n & (HD - 1);
                    const float2 rcv = *(const float2*)(rc + t*HD + d);
                    const float o0 = (v0 * rcv.y - v1 * rcv.x) * postscale;
                    const float o1 = (v1 * rcv.y + v0 * rcv.x) * postscale;
                    v0 = o0; v1 = o1;
                }
                if (mode == 0) {
                    float2 sv; sv.x = v0; sv.y = v1;
                    *(float2*)(outf + (size_t)r * ldo + n) = sv;
                } else {
                    const __nv_bfloat16 h0 = __float2bfloat16(v0);
                    const __nv_bfloat16 h1 = __float2bfloat16(v1);
                    const __nv_bfloat16 l0 = __float2bfloat16(v0 - __bfloat162float(h0));
                    const __nv_bfloat16 l1 = __float2bfloat16(v1 - __bfloat162float(h1));
                    if (mode == 1) {
                        __nv_bfloat162 hh; hh.x = h0; hh.y = h1;
                        __nv_bfloat162 ll; ll.x = l0; ll.y = l1;
                        *(__nv_bfloat162*)(outh + (size_t)r * ldo + n) = hh;
                        *(__nv_bfloat162*)(outl + (size_t)r * ldo + n) = ll;
                    } else {  // mode 2: V transposed [b][hk][d][t]
                        const int bb = r >> 11, t = r & (TT - 1);
                        const int hkv = n >> 6, d = n & (HD - 1);
                        const size_t base = (((size_t)bb*HKV + hkv)*HD + d)*TT + t;
                        outh[base] = h0; outh[base + TT] = h1;
                        outl[base] = l0; outl[base + TT] = l1;
                    }
                }
            }
        }
    }
}

// grid (10, 32): x 0..7 -> Q col tiles, 8 -> K, 9 -> V
__global__ __launch_bounds__(256) void qkv_hmma_kernel(
    const float* __restrict__ rc,
    const float* __restrict__ bq, const float* __restrict__ bk,
    const float* __restrict__ bv)
{
    const int nb = blockIdx.x, m0 = blockIdx.y * 128;
    if (nb < 8)
        hmma_tile_128(g_xh, g_xl, g_wqh, g_wql, bq, rc, m0, nb*128, HQ*HD,
                      1, 1.0f/(float)HD, nullptr, g_qbh, g_qbl);
    else if (nb == 8)
        hmma_tile_128(g_xh, g_xl, g_wkh, g_wkl, bk, rc, m0, 0, HKV*HD,
                      1, 1.0f, nullptr, g_kbh, g_kbl);
    else
        hmma_tile_128(g_xh, g_xl, g_wvh, g_wvl, bv, nullptr, m0, 0, HKV*HD,
                      2, 1.0f, nullptr, g_vth, g_vtl);
}

__global__ __launch_bounds__(256) void oproj_hmma_kernel(
    const float* __restrict__ bo, float* __restrict__ out)
{
    hmma_tile_128(g_yh, g_yl, g_woh, g_wol, bo, nullptr,
                  blockIdx.y*128, blockIdx.x*128, CC, 0, 1.0f,
                  out, nullptr, nullptr);
}

// ---------------------------------------------------------------------------
// Flash attention on HMMA. grid (T/64, HQ, B), 128 threads (4 warps).
// Warp w owns q-rows 16w..16w+15. BK=64. 3-term split-bf16 for S and PV.
// O accumulated transposed (O^T = V^T P^T); P stays in registers.
// ---------------------------------------------------------------------------
#define FP 72                       // smem pitch in bf16 (144 B)
#define MATB (64*FP*2)              // 9216 B per matrix
#define FLASH_SMEM (6*MATB)         // 55296 B

__global__ __launch_bounds__(128) void flash_hmma_kernel()
{
    extern __shared__ __nv_bfloat16 fsm[];
    const u32 sb = smem_to_u32(fsm);
    // matrices: Qh@0, Ql@MATB, Kh@2*MATB, Kl@3*MATB, Vth@4*MATB, Vtl@5*MATB

    const int qb = blockIdx.x, h = blockIdx.y, b = blockIdx.z;
    const int qs = qb * 64;
    const int hk = h / (HQ / HKV);
    const int tid = threadIdx.x, wid = tid >> 5, L = tid & 31;

    // stage Q (64 rows x 64 bf16, hi+lo)
    for (int it = tid; it < 512; it += 128) {
        const int row = it >> 3, ch = it & 7;
        const size_t src = (((size_t)b*TT + qs + row)*HQ + h)*HD + ch*8;
        *(float4*)&fsm[row*FP + ch*8]            = *(const float4*)(g_qbh + src);
        *(float4*)&fsm[64*FP + row*FP + ch*8]    = *(const float4*)(g_qbl + src);
    }

    // fragment address offsets (bytes)
    const u32 aQoff = (u32)((wid*16 + (L & 15)) * SPB) + ((L >> 4) & 1) * 16;
    const u32 aVrow = (u32)((L & 15) * SPB) + ((L >> 4) & 1) * 16;
    const u32 bKoff = (u32)((((L >> 4) & 1) * 8 + (L & 7)) * SPB) + ((L >> 3) & 1) * 16;

    float m0 = -1e30f, m1 = -1e30f, ls0 = 0.f, ls1 = 0.f;
    float oacc[4][2][4];
    #pragma unroll
    for (int i = 0; i < 4; ++i)
        #pragma unroll
        for (int j = 0; j < 2; ++j)
            #pragma unroll
            for (int c = 0; c < 4; ++c) oacc[i][j][c] = 0.f;

    for (int kt = 0; kt <= qb; ++kt) {
        __syncthreads();
        // stage K (rows t), V^T (rows d)
        for (int it = tid; it < 512; it += 128) {
            const int row = it >> 3, ch = it & 7;
            const size_t ks = (((size_t)b*TT + kt*64 + row)*HKV + hk)*HD + ch*8;
            const size_t vs = (((size_t)b*HKV + hk)*HD + row)*TT + kt*64 + ch*8;
            *(float4*)&fsm[2*64*FP + row*FP + ch*8] = *(const float4*)(g_kbh + ks);
            *(float4*)&fsm[3*64*FP + row*FP + ch*8] = *(const float4*)(g_kbl + ks);
            *(float4*)&fsm[4*64*FP + row*FP + ch*8] = *(const float4*)(g_vth + vs);
            *(float4*)&fsm[5*64*FP + row*FP + ch*8] = *(const float4*)(g_vtl + vs);
        }
        __syncthreads();

        // ---- S = Q.K^T (3-term) ----
        float sacc[8][4];
        #pragma unroll
        for (int nt = 0; nt < 8; ++nt)
            #pragma unroll
            for (int c = 0; c < 4; ++c) sacc[nt][c] = 0.f;

        #pragma unroll
        for (int ks = 0; ks < 4; ++ks) {
            u32 qh_[4], ql_[4];
            ldm_x4(qh_, sb + aQoff + ks*32);
            ldm_x4(ql_, sb + MATB + aQoff + ks*32);
            #pragma unroll
            for (int np = 0; np < 4; ++np) {
                u32 rh[4], rl[4];
                const u32 bo = (u32)(np*16*SPB) + bKoff + ks*32;
                ldm_x4(rh, sb + 2*MATB + bo);
                ldm_x4(rl, sb + 3*MATB + bo);
                u32 bh0[2] = { rh[0], rh[1] }, bh1[2] = { rh[2], rh[3] };
                u32 bl0[2] = { rl[0], rl[1] }, bl1[2] = { rl[2], rl[3] };
                hmma(sacc[2*np],   qh_, bh0);
                hmma(sacc[2*np],   qh_, bl0);
                hmma(sacc[2*np],   ql_, bh0);
                hmma(sacc[2*np+1], qh_, bh1);
                hmma(sacc[2*np+1], qh_, bl1);
                hmma(sacc[2*np+1], ql_, bh1);
            }
        }

        // ---- causal mask (diagonal tile only) ----
        if (kt == qb) {
            #pragma unroll
            for (int nt = 0; nt < 8; ++nt)
                #pragma unroll
                for (int c = 0; c < 4; ++c) {
                    const int col = nt*8 + (L & 3)*2 + (c & 1);
                    const int row = wid*16 + (L >> 2) + ((c >> 1) & 1)*8;
                    if (col > row) sacc[nt][c] = -1e30f;
                }
        }

        // ---- online softmax (rows r=L/4 -> half0, r+8 -> half1) ----
        float mx0 = -1e30f, mx1 = -1e30f;
        #pragma unroll
        for (int nt = 0; nt < 8; ++nt) {
            mx0 = fmaxf(mx0, fmaxf(sacc[nt][0], sacc[nt][1]));
            mx1 = fmaxf(mx1, fmaxf(sacc[nt][2], sacc[nt][3]));
        }
        mx0 = fmaxf(mx0, __shfl_xor_sync(0xffffffffu, mx0, 1));
        mx0 = fmaxf(mx0, __shfl_xor_sync(0xffffffffu, mx0, 2));
        mx1 = fmaxf(mx1, __shfl_xor_sync(0xffffffffu, mx1, 1));
        mx1 = fmaxf(mx1, __shfl_xor_sync(0xffffffffu, mx1, 2));
        const float nm0 = fmaxf(m0, mx0);
        const float nm1 = fmaxf(m1, mx1);
        const float corr0 = __expf(m0 - nm0);
        const float corr1 = __expf(m1 - nm1);
        m0 = nm0; m1 = nm1;

        u32 ph0[8], ph1[8], pl0[8], pl1[8];
        float rs0 = 0.f, rs1 = 0.f;
        #pragma unroll
        for (int nt = 0; nt < 8; ++nt) {
            const float p00 = __expf(sacc[nt][0] - nm0);
            const float p01 = __expf(sacc[nt][1] - nm0);
            const float p10 = __expf(sacc[nt][2] - nm1);
            const float p11 = __expf(sacc[nt][3] - nm1);
            rs0 += p00 + p01;
            rs1 += p10 + p11;
            ph0[nt] = cvt2(p01, p00);
            ph1[nt] = cvt2(p11, p10);
            pl0[nt] = cvt2(p01 - __bfloat162float(__float2bfloat16(p01)),
                           p00 - __bfloat162float(__float2bfloat16(p00)));
            pl1[nt] = cvt2(p11 - __bfloat162float(__float2bfloat16(p11)),
                           p10 - __bfloat162float(__float2bfloat16(p10)));
        }
        rs0 += __shfl_xor_sync(0xffffffffu, rs0, 1);
        rs0 += __shfl_xor_sync(0xffffffffu, rs0, 2);
        rs1 += __shfl_xor_sync(0xffffffffu, rs1, 1);
        rs1 += __shfl_xor_sync(0xffffffffu, rs1, 2);
        ls0 = ls0 * corr0 + rs0;
        ls1 = ls1 * corr1 + rs1;

        // rescale O^T accumulators: need corr for i = (L&3)*2+e (slot = ntile)
        float cr[2][2];
        cr[0][0] = __shfl_sync(0xffffffffu, corr0, ((L & 3)*2)     << 2);
        cr[0][1] = __shfl_sync(0xffffffffu, corr0, ((L & 3)*2 + 1) << 2);
        cr[1][0] = __shfl_sync(0xffffffffu, corr1, ((L & 3)*2)     << 2);
        cr[1][1] = __shfl_sync(0xffffffffu, corr1, ((L & 3)*2 + 1) << 2);
        #pragma unroll
        for (int mt = 0; mt < 4; ++mt)
            #pragma unroll
            for (int nu = 0; nu < 2; ++nu)
                #pragma unroll
                for (int c = 0; c < 4; ++c)
                    oacc[mt][nu][c] *= cr[nu][c & 1];

        // ---- O^T += V^T.P^T (3-term) ----
        #pragma unroll
        for (int k2 = 0; k2 < 4; ++k2) {
            u32 bH0[2] = { ph0[2*k2], ph0[2*k2+1] };
            u32 bH1[2] = { ph1[2*k2], ph1[2*k2+1] };
            u32 bL0[2] = { pl0[2*k2], pl0[2*k2+1] };
            u32 bL1[2] = { pl1[2*k2], pl1[2*k2+1] };
            #pragma unroll
            for (int mt = 0; mt < 4; ++mt) {
                u32 vh_[4], vl_[4];
                const u32 vo = aVrow + (u32)(mt*16*SPB) + k2*32;
                ldm_x4(vh_, sb + 4*MATB + vo);
                ldm_x4(vl_, sb + 5*MATB + vo);
                hmma(oacc[mt][0], vh_, bH0);
                hmma(oacc[mt][0], vl_, bH0);
                hmma(oacc[mt][0], vh_, bL0);
                hmma(oacc[mt][1], vh_, bH1);
                hmma(oacc[mt][1], vl_, bH1);
                hmma(oacc[mt][1], vh_, bL1);
            }
        }
    }

    // ---- normalize + write y (fp32, [b][t][h][d]) ----
    const float rl0 = 1.f / ls0, rl1 = 1.f / ls1;
    float iv[2][2];
    iv[0][0] = __shfl_sync(0xffffffffu, rl0, ((L & 3)*2)     << 2);
    iv[0][1] = __shfl_sync(0xffffffffu, rl0, ((L & 3)*2 + 1) << 2);
    iv[1][0] = __shfl_sync(0xffffffffu, rl1, ((L & 3)*2)     << 2);
    iv[1][1] = __shfl_sync(0xffffffffu, rl1, ((L & 3)*2 + 1) << 2);
    #pragma unroll
    for (int mt = 0; mt < 4; ++mt)
        #pragma unroll
        for (int nu = 0; nu < 2; ++nu)
            #pragma unroll
            for (int c = 0; c < 4; ++c) {
                const int d = mt*16 + (L >> 2) + ((c >> 1) & 1)*8;
                const int i = nu*8 + (L & 3)*2 + (c & 1);
                g_y[(((size_t)b*TT + qs + wid*16 + i)*HQ + h)*HD + d] =
                    oacc[mt][nu][c] * iv[nu][c & 1];
            }
}

// ---------------------------------------------------------------------------
extern "C" void kernel_launch(void* const* d_in, const int* in_sizes, int n_in,
                              void* d_out, int out_size)
{
    const float* x  = (const float*)d_in[0];
    const float* rc = (const float*)d_in[1];
    const float* Wq = (const float*)d_in[2];
    const float* bq = (const float*)d_in[3];
    const float* Wk = (const float*)d_in[4];
    const float* bk = (const float*)d_in[5];
    const float* Wv = (const float*)d_in[6];
    const float* bv = (const float*)d_in[7];
    const float* Wo = (const float*)d_in[8];
    const float* bo = (const float*)d_in[9];
    float* out = (float*)d_out;

    __nv_bfloat16 *xh, *xl, *yh, *yl, *wqh, *wql, *wkh, *wkl, *wvh, *wvl, *woh, *wol;
    float* yb;
    cudaGetSymbolAddress((void**)&xh,  g_xh);  cudaGetSymbolAddress((void**)&xl,  g_xl);
    cudaGetSymbolAddress((void**)&yh,  g_yh);  cudaGetSymbolAddress((void**)&yl,  g_yl);
    cudaGetSymbolAddress((void**)&wqh, g_wqh); cudaGetSymbolAddress((void**)&wql, g_wql);
    cudaGetSymbolAddress((void**)&wkh, g_wkh); cudaGetSymbolAddress((void**)&wkl, g_wkl);
    cudaGetSymbolAddress((void**)&wvh, g_wvh); cudaGetSymbolAddress((void**)&wvl, g_wvl);
    cudaGetSymbolAddress((void**)&woh, g_woh); cudaGetSymbolAddress((void**)&wol, g_wol);
    cudaGetSymbolAddress((void**)&yb,  g_y);

    cudaFuncSetAttribute(qkv_hmma_kernel,
                         cudaFuncAttributeMaxDynamicSharedMemorySize, HMMA_SMEM);
    cudaFuncSetAttribute(oproj_hmma_kernel,
                         cudaFuncAttributeMaxDynamicSharedMemorySize, HMMA_SMEM);
    cudaFuncSetAttribute(flash_hmma_kernel,
                         cudaFuncAttributeMaxDynamicSharedMemorySize, FLASH_SMEM);

    // Split fp32 -> bf16 (hi, lo)
    split_kernel<<<(MROWS*CC/4 + 255)/256, 256>>>(x,  xh,  xl,  MROWS*CC/4);
    split_kernel<<<(CC*CC/4 + 255)/256, 256>>>(Wq, wqh, wql, CC*CC/4);
    split_kernel<<<(HKV*HD*CC/4 + 255)/256, 256>>>(Wk, wkh, wkl, HKV*HD*CC/4);
    split_kernel<<<(HKV*HD*CC/4 + 255)/256, 256>>>(Wv, wvh, wvl, HKV*HD*CC/4);
    split_kernel<<<(CC*CC/4 + 255)/256, 256>>>(Wo, woh, wol, CC*CC/4);

    // QKV projection + bias + RoPE, writing split-bf16 Q/K and transposed V
    qkv_hmma_kernel<<<dim3(10, MROWS/128), 256, HMMA_SMEM>>>(rc, bq, bk, bv);

    // Causal flash attention (HMMA, 3-term split-bf16)
    flash_hmma_kernel<<<dim3(TT/64, HQ, BB), 128, FLASH_SMEM>>>();

    // Output projection (HMMA, split-bf16)
    split_kernel<<<(MROWS*CC/4 + 255)/256, 256>>>(yb, yh, yl, MROWS*CC/4);
    oproj_hmma_kernel<<<dim3(CC/128, MROWS/128), 256, HMMA_SMEM>>>(bo, out);
}